// round 15
// baseline (speedup 1.0000x reference)
#include <cuda_runtime.h>
#include <math.h>

// Problem dims (fixed)
#define T_DIM 4
#define B_DIM 16
#define N_TOK 256
#define C_DIM 512
#define HID_DIM 2048
#define H_HEADS 8
#define HD 64
#define M_ROWS (T_DIM * B_DIM * N_TOK)   // 16384
#define RN (B_DIM * N_TOK)               // 4096
#define NTILE 128                        // 16384 = 128 tiles x 128 rows
#define NC (M_ROWS * C_DIM)              // 8,388,608
#define PSLICE (NTILE * HID_DIM)         // 262144: max partial slice (f1)

// ---------------------------------------------------------------------------
// Scratch (device globals; no runtime allocation allowed)
// ---------------------------------------------------------------------------
__device__ float  g_scratch[(size_t)M_ROWS * HID_DIM];
__device__ float  g_qs[(size_t)M_ROWS * C_DIM];
__device__ float  g_ks[(size_t)M_ROWS * C_DIM];
__device__ float  g_vs[(size_t)M_ROWS * C_DIM];
__device__ float  g_ob[(size_t)M_ROWS * C_DIM];
__device__ float  g_x1[(size_t)M_ROWS * C_DIM];
__device__ float  g_pm[3 * NTILE * C_DIM > PSLICE ? 3 * NTILE * C_DIM : PSLICE]; // mean partials
__device__ float  g_pv[3 * NTILE * C_DIM > PSLICE ? 3 * NTILE * C_DIM : PSLICE]; // var partials
__device__ float  g_mean[3 * C_DIM > HID_DIM ? 3 * C_DIM : HID_DIM];
__device__ float  g_rs[3 * C_DIM > HID_DIM ? 3 * C_DIM : HID_DIM];

// ---------------------------------------------------------------------------
// SGEMM + fused BN mean-stage1.  Y[M,N] = A[M,K] @ W[K,N] + bias.
// Double-buffered smem, 128x128x16, 8x8/thread, scalar ascending-k FFMA
// chain per output with bias added last (FROZEN numerics, R13-proven).
// Epilogue: each block re-reduces its own 128x128 Y tile with the exact XLA
// stage-1 shape (lane=rowlane sums rows +0,+32,+64,+96 in order; shfl-down
// tree 16..1; lane0 writes the tile partial).  Bit-identical to the
// standalone bn_stage1 mean kernel it replaces.
// grid.z selects (W,b), Y slice, and partial slice (merged q/k/v).
// ---------------------------------------------------------------------------
__global__ void __launch_bounds__(256)
sgemm_bias_mean(const float* __restrict__ A,
                const float* __restrict__ W0, const float* __restrict__ W1,
                const float* __restrict__ W2,
                const float* __restrict__ b0, const float* __restrict__ b1,
                const float* __restrict__ b2,
                float* __restrict__ Y, float* __restrict__ Pm,
                int M, int N, int K, int ysl)
{
    const int BM = 128, BN = 128, BK = 16, TM = 8, TN = 8;
    __shared__ __align__(16) float As[2][BK][BM];
    __shared__ __align__(16) float Bs[2][BK][BN];

    const int tid = threadIdx.x;
    const int z   = blockIdx.z;
    const float* W    = (z == 0) ? W0 : (z == 1 ? W1 : W2);
    const float* bias = (z == 0) ? b0 : (z == 1 ? b1 : b2);
    float* Yz = Y + (size_t)z * ysl;

    const int trow = (tid / 16) * TM;
    const int tcol = (tid % 16) * TN;
    const float* Ab = A + (size_t)blockIdx.y * BM * K;
    const float* Wb = W + (size_t)blockIdx.x * BN;

    float4 ra[2], rb[2];

#define LOAD_TILE(kt)                                                        \
    {                                                                        \
        _Pragma("unroll")                                                    \
        for (int i = 0; i < 2; i++) {                                        \
            int idx4 = tid + 256 * i;                                        \
            int r  = idx4 >> 2, c4 = (idx4 & 3) * 4;                         \
            ra[i] = *reinterpret_cast<const float4*>(                        \
                &Ab[(size_t)r * K + (kt) * BK + c4]);                        \
            int r2 = idx4 >> 5, c42 = (idx4 & 31) * 4;                       \
            rb[i] = *reinterpret_cast<const float4*>(                        \
                &Wb[(size_t)((kt) * BK + r2) * N + c42]);                    \
        }                                                                    \
    }

#define STORE_TILE(buf)                                                      \
    {                                                                        \
        _Pragma("unroll")                                                    \
        for (int i = 0; i < 2; i++) {                                        \
            int idx4 = tid + 256 * i;                                        \
            int r  = idx4 >> 2, c4 = (idx4 & 3) * 4;                         \
            As[buf][c4 + 0][r] = ra[i].x;                                    \
            As[buf][c4 + 1][r] = ra[i].y;                                    \
            As[buf][c4 + 2][r] = ra[i].z;                                    \
            As[buf][c4 + 3][r] = ra[i].w;                                    \
            int r2 = idx4 >> 5, c42 = (idx4 & 31) * 4;                       \
            *reinterpret_cast<float4*>(&Bs[buf][r2][c42]) = rb[i];           \
        }                                                                    \
    }

    float acc[TM][TN];
#pragma unroll
    for (int i = 0; i < TM; i++)
#pragma unroll
        for (int j = 0; j < TN; j++) acc[i][j] = 0.f;

    LOAD_TILE(0);
    STORE_TILE(0);
    __syncthreads();

    const int nt = K / BK;
    for (int t = 0; t < nt; t++) {
        const int cur = t & 1;
        if (t + 1 < nt) LOAD_TILE(t + 1);

#pragma unroll
        for (int k = 0; k < BK; k++) {
            float4 a0 = *reinterpret_cast<const float4*>(&As[cur][k][trow]);
            float4 a1 = *reinterpret_cast<const float4*>(&As[cur][k][trow + 4]);
            float4 b0v = *reinterpret_cast<const float4*>(&Bs[cur][k][tcol]);
            float4 b1v = *reinterpret_cast<const float4*>(&Bs[cur][k][tcol + 4]);
            float a[8] = {a0.x, a0.y, a0.z, a0.w, a1.x, a1.y, a1.z, a1.w};
            float b[8] = {b0v.x, b0v.y, b0v.z, b0v.w, b1v.x, b1v.y, b1v.z, b1v.w};
#pragma unroll
            for (int i = 0; i < TM; i++)
#pragma unroll
                for (int j = 0; j < TN; j++)
                    acc[i][j] = __fmaf_rn(a[i], b[j], acc[i][j]);
        }

        if (t + 1 < nt) {
            STORE_TILE(cur ^ 1);
            __syncthreads();
        }
    }

#pragma unroll
    for (int i = 0; i < TM; i++) {
        size_t row = (size_t)blockIdx.y * BM + trow + i;
#pragma unroll
        for (int j = 0; j < TN; j++) {
            int col = blockIdx.x * BN + tcol + j;
            Yz[row * N + col] = __fadd_rn(acc[i][j], bias[col]);
        }
    }

    // ---- fused BN mean stage-1 over this block's 128x128 tile ----
    __syncthreads();   // Y tile writes visible block-wide
    {
        const int wid  = tid >> 5;
        const int lane = tid & 31;
        const int rowbase = blockIdx.y * BM;
        const int colbase = blockIdx.x * BN;
        float* Pz = Pm + (size_t)z * PSLICE;
#pragma unroll 2
        for (int it = 0; it < 16; it++) {
            int c = colbase + it * 8 + wid;
            float a = 0.f;
#pragma unroll
            for (int i = 0; i < 4; i++)
                a = __fadd_rn(a, Yz[(size_t)(rowbase + lane + 32 * i) * N + c]);
#pragma unroll
            for (int off = 16; off; off >>= 1)
                a = __fadd_rn(a, __shfl_down_sync(0xffffffffu, a, off));
            if (lane == 0)
                Pz[(size_t)blockIdx.y * N + c] = a;
        }
    }
#undef LOAD_TILE
#undef STORE_TILE
}

// ---------------------------------------------------------------------------
// var stage-1 with fused mean stage-2 (FROZEN numerics):
//   1) recompute mean for this block's 32 columns from the mean partials with
//      the exact stage-2 sequence (4-strided serial sums + transpose + tree);
//      tile-0 blocks also store g_mean for the LIF.
//   2) var partial over this tile: separately-rounded (x-mean)^2, same shape.
// ---------------------------------------------------------------------------
__global__ void __launch_bounds__(1024)
bn_var1(const float* __restrict__ Y, const float* __restrict__ Pm,
        float* __restrict__ Pv, int C, int ysl)
{
    __shared__ float sm[32][33];
    __shared__ float mean_sm[32];
    const int z    = blockIdx.z;
    const int c0   = blockIdx.x * 32;
    const int tile = blockIdx.y;
    const int tx = threadIdx.x;
    const int ty = threadIdx.y;
    const float* Yz  = Y  + (size_t)z * ysl;
    const float* Pmz = Pm + (size_t)z * PSLICE;
    float*       Pvz = Pv + (size_t)z * PSLICE;

    // mean stage-2 (recomputed; bit-identical to the standalone kernel)
    float am = 0.f;
#pragma unroll
    for (int i = 0; i < 4; i++)
        am = __fadd_rn(am, Pmz[(size_t)(ty + 32 * i) * C + c0 + tx]);
    sm[ty][tx] = am;
    __syncthreads();
    float vm = sm[tx][ty];
#pragma unroll
    for (int off = 16; off; off >>= 1)
        vm = __fadd_rn(vm, __shfl_down_sync(0xffffffffu, vm, off));
    if (tx == 0) {
        float mean = __fmul_rn(vm, 6.103515625e-05f);   // /16384, exact
        mean_sm[ty] = mean;
        if (tile == 0)
            g_mean[z * C + c0 + ty] = mean;
    }
    __syncthreads();
    const float m = mean_sm[tx];

    // var stage-1 partial
    float acc = 0.f;
#pragma unroll
    for (int i = 0; i < 4; i++) {
        int r = tile * 128 + ty + i * 32;
        float d  = __fsub_rn(Yz[(size_t)r * C + c0 + tx], m);
        float sq = __fmul_rn(d, d);       // separate fp32 rounding (no FMA)
        acc = __fadd_rn(acc, sq);
    }
    __syncthreads();                      // sm reuse
    sm[ty][tx] = acc;
    __syncthreads();
    float v = sm[tx][ty];
#pragma unroll
    for (int off = 16; off; off >>= 1)
        v = __fadd_rn(v, __shfl_down_sync(0xffffffffu, v, off));
    if (tx == 0)
        Pvz[(size_t)tile * C + c0 + ty] = v;
}

// var stage-2: reduce 128 var partials per channel; rs = rsqrtf(var+eps).
__global__ void __launch_bounds__(1024)
bn_var2(const float* __restrict__ Pv, int C)
{
    __shared__ float sm[32][33];
    const int z  = blockIdx.z;
    const int c0 = blockIdx.x * 32;
    const int tx = threadIdx.x;
    const int ty = threadIdx.y;
    const float* Pvz = Pv + (size_t)z * PSLICE;

    float acc = 0.f;
#pragma unroll
    for (int i = 0; i < 4; i++)
        acc = __fadd_rn(acc, Pvz[(size_t)(ty + 32 * i) * C + c0 + tx]);
    sm[ty][tx] = acc;
    __syncthreads();
    float v = sm[tx][ty];
#pragma unroll
    for (int off = 16; off; off >>= 1)
        v = __fadd_rn(v, __shfl_down_sync(0xffffffffu, v, off));
    if (tx == 0) {
        float var = __fmul_rn(v, 6.103515625e-05f);     // exact
        float arg = __fadd_rn(var, 1e-5f);
        g_rs[z * C + c0 + ty] = rsqrtf(arg);            // libdevice (FROZEN)
    }
}

// ---------------------------------------------------------------------------
// LIF over T=4 (FROZEN numerics) with optional fused residual add.
// ---------------------------------------------------------------------------
__global__ void lif_kernel(const float* __restrict__ Y, float* __restrict__ OUT,
                           const float* __restrict__ RES,
                           const float* __restrict__ gamma,
                           const float* __restrict__ beta,
                           int Cout, int use_bn, int soff)
{
    int idx = blockIdx.x * blockDim.x + threadIdx.x;
    int total = RN * Cout;
    if (idx >= total) return;
    int c = idx & (Cout - 1);
    float mean = 0.f, rs = 1.f, ga = 1.f, be = 0.f;
    if (use_bn) {
        mean = g_mean[soff + c]; rs = g_rs[soff + c];
        ga = gamma[c]; be = beta[c];
    }
    size_t stride = (size_t)RN * Cout;

    float mem = 0.f;
#pragma unroll
    for (int t = 0; t < T_DIM; t++) {
        size_t g = (size_t)t * stride + idx;
        float h = Y[g];
        float pre;
        if (use_bn) {
            float n1 = __fmul_rn(__fsub_rn(h, mean), rs);
            pre = __fmaf_rn(n1, ga, be);
        } else {
            pre = h;
        }
        mem = __fmaf_rn(__fsub_rn(pre, mem), 0.5f, mem);   // TAU=2
        float d = __fsub_rn(mem, 1.0f);
        float spk = (d > 0.f) ? 1.0f : 0.0f;
        if (spk > 0.f) mem = 0.f;
        OUT[g] = RES ? __fadd_rn(RES[g], spk) : spk;
    }
}

// ---------------------------------------------------------------------------
// Spiking self-attention (exact integer arithmetic; FROZEN).
// ---------------------------------------------------------------------------
__global__ void __launch_bounds__(256)
attn_kernel(const float* __restrict__ Q, const float* __restrict__ K,
            const float* __restrict__ V, float* __restrict__ O)
{
    const int h  = blockIdx.x;
    const int tb = blockIdx.y;
    const size_t base = (size_t)tb * N_TOK * C_DIM + (size_t)h * HD;

    __shared__ float KV[64 * 64];
    __shared__ float pool[64 * 65];
    float* Ks = pool;
    float* Vs = pool + 2048;

    const int tid = threadIdx.x;

    float acc[16];
#pragma unroll
    for (int j = 0; j < 16; j++) acc[j] = 0.f;
    const int d1  = tid >> 2;
    const int d2b = (tid & 3) * 16;

    for (int n0 = 0; n0 < N_TOK; n0 += 32) {
#pragma unroll
        for (int i = tid; i < 32 * 64; i += 256) {
            int r = i >> 6, d = i & 63;
            size_t g = base + (size_t)(n0 + r) * C_DIM + d;
            Ks[i] = K[g];
            Vs[i] = V[g];
        }
        __syncthreads();
#pragma unroll
        for (int n = 0; n < 32; n++) {
            float a = Ks[n * 64 + d1];
#pragma unroll
            for (int j = 0; j < 16; j++)
                acc[j] += a * Vs[n * 64 + d2b + j];
        }
        __syncthreads();
    }
#pragma unroll
    for (int j = 0; j < 16; j++)
        KV[d1 * 64 + d2b + j] = acc[j];
    __syncthreads();

    const int trow = (tid >> 4) * 4;
    const int tcol = (tid & 15) * 4;
    float* Qs = pool;

    for (int rb = 0; rb < 4; rb++) {
#pragma unroll
        for (int i = tid; i < 64 * 64; i += 256) {
            int r = i >> 6, d = i & 63;
            Qs[r * 65 + d] = Q[base + (size_t)(rb * 64 + r) * C_DIM + d];
        }
        __syncthreads();

        float o[4][4];
#pragma unroll
        for (int i = 0; i < 4; i++)
#pragma unroll
            for (int j = 0; j < 4; j++) o[i][j] = 0.f;

#pragma unroll
        for (int k = 0; k < 64; k++) {
            float a[4], b[4];
#pragma unroll
            for (int i = 0; i < 4; i++) a[i] = Qs[(trow + i) * 65 + k];
#pragma unroll
            for (int j = 0; j < 4; j++) b[j] = KV[k * 64 + tcol + j];
#pragma unroll
            for (int i = 0; i < 4; i++)
#pragma unroll
                for (int j = 0; j < 4; j++)
                    o[i][j] += a[i] * b[j];
        }
#pragma unroll
        for (int i = 0; i < 4; i++)
#pragma unroll
            for (int j = 0; j < 4; j++)
                O[base + (size_t)(rb * 64 + trow + i) * C_DIM + tcol + j] = 0.125f * o[i][j];
        __syncthreads();
    }
}

// ---------------------------------------------------------------------------
// Launcher
// ---------------------------------------------------------------------------
static float* s_pm = 0;
static float* s_pv = 0;

static void run_stats(const float* Y, int C, int zc, int ysl)
{
    dim3 sblk(32, 32);
    bn_var1<<<dim3(C / 32, NTILE, zc), sblk>>>(Y, s_pm, s_pv, C, ysl);
    bn_var2<<<dim3(C / 32, 1, zc), sblk>>>(s_pv, C);
}

extern "C" void kernel_launch(void* const* d_in, const int* in_sizes, int n_in,
                              void* d_out, int out_size)
{
    const float* x    = (const float*)d_in[0];
    const float* qW   = (const float*)d_in[1];
    const float* qb   = (const float*)d_in[2];
    const float* qg   = (const float*)d_in[3];
    const float* qbe  = (const float*)d_in[4];
    const float* kW   = (const float*)d_in[5];
    const float* kb   = (const float*)d_in[6];
    const float* kg   = (const float*)d_in[7];
    const float* kbe  = (const float*)d_in[8];
    const float* vW   = (const float*)d_in[9];
    const float* vb   = (const float*)d_in[10];
    const float* vg   = (const float*)d_in[11];
    const float* vbe  = (const float*)d_in[12];
    const float* pW   = (const float*)d_in[13];
    const float* pb   = (const float*)d_in[14];
    const float* pg   = (const float*)d_in[15];
    const float* pbe  = (const float*)d_in[16];
    const float* f1W  = (const float*)d_in[17];
    const float* f1b  = (const float*)d_in[18];
    const float* f1g  = (const float*)d_in[19];
    const float* f1be = (const float*)d_in[20];
    const float* f2W  = (const float*)d_in[21];
    const float* f2b  = (const float*)d_in[22];
    const float* f2g  = (const float*)d_in[23];
    const float* f2be = (const float*)d_in[24];
    float* out = (float*)d_out;

    float *scratch, *qs, *ks, *vs, *ob, *x1;
    cudaGetSymbolAddress((void**)&scratch, g_scratch);
    cudaGetSymbolAddress((void**)&qs, g_qs);
    cudaGetSymbolAddress((void**)&ks, g_ks);
    cudaGetSymbolAddress((void**)&vs, g_vs);
    cudaGetSymbolAddress((void**)&ob, g_ob);
    cudaGetSymbolAddress((void**)&x1, g_x1);
    cudaGetSymbolAddress((void**)&s_pm, g_pm);
    cudaGetSymbolAddress((void**)&s_pv, g_pv);

    const int LIF_BLOCKS = (RN * C_DIM + 255) / 256;

    // --- SSA: q,k,v projections merged (grid.z=3), mean-stage1 fused ---
    sgemm_bias_mean<<<dim3(C_DIM / 128, M_ROWS / 128, 3), 256>>>(
        x, qW, kW, vW, qb, kb, vb, scratch, s_pm, M_ROWS, C_DIM, C_DIM, NC);
    run_stats(scratch, C_DIM, 3, NC);
    lif_kernel<<<LIF_BLOCKS, 256>>>(scratch,                  qs, (const float*)0, qg, qbe, C_DIM, 1, 0);
    lif_kernel<<<LIF_BLOCKS, 256>>>(scratch + (size_t)NC,     ks, (const float*)0, kg, kbe, C_DIM, 1, C_DIM);
    lif_kernel<<<LIF_BLOCKS, 256>>>(scratch + (size_t)2 * NC, vs, (const float*)0, vg, vbe, C_DIM, 1, 2 * C_DIM);

    // --- attention + its LIF (exact) ---
    attn_kernel<<<dim3(H_HEADS, T_DIM * B_DIM), 256>>>(qs, ks, vs, ob);
    lif_kernel<<<LIF_BLOCKS, 256>>>(ob, ob, (const float*)0,
                                    (const float*)0, (const float*)0, C_DIM, 0, 0);

    // --- projection p; LIF fused with residual: x1 = x + spk ---
    sgemm_bias_mean<<<dim3(C_DIM / 128, M_ROWS / 128, 1), 256>>>(
        ob, pW, pW, pW, pb, pb, pb, scratch, s_pm, M_ROWS, C_DIM, C_DIM, 0);
    run_stats(scratch, C_DIM, 1, 0);
    lif_kernel<<<LIF_BLOCKS, 256>>>(scratch, x1, x, pg, pbe, C_DIM, 1, 0);

    // --- MLP f1 (512->2048), LIF in-place ---
    sgemm_bias_mean<<<dim3(HID_DIM / 128, M_ROWS / 128, 1), 256>>>(
        x1, f1W, f1W, f1W, f1b, f1b, f1b, scratch, s_pm, M_ROWS, HID_DIM, C_DIM, 0);
    run_stats(scratch, HID_DIM, 1, 0);
    lif_kernel<<<(RN * HID_DIM + 255) / 256, 256>>>(
        scratch, scratch, (const float*)0, f1g, f1be, HID_DIM, 1, 0);

    // --- MLP f2 (2048->512); LIF fused with final residual: out = x1 + spk ---
    sgemm_bias_mean<<<dim3(C_DIM / 128, M_ROWS / 128, 1), 256>>>(
        scratch, f2W, f2W, f2W, f2b, f2b, f2b, vs, s_pm, M_ROWS, C_DIM, HID_DIM, 0);
    run_stats(vs, C_DIM, 1, 0);
    lif_kernel<<<LIF_BLOCKS, 256>>>(vs, out, x1, f2g, f2be, C_DIM, 1, 0);
}

// round 16
// speedup vs baseline: 1.0509x; 1.0509x over previous
#include <cuda_runtime.h>
#include <math.h>

// Problem dims (fixed)
#define T_DIM 4
#define B_DIM 16
#define N_TOK 256
#define C_DIM 512
#define HID_DIM 2048
#define H_HEADS 8
#define HD 64
#define M_ROWS (T_DIM * B_DIM * N_TOK)   // 16384
#define RN (B_DIM * N_TOK)               // 4096
#define NTILE 128                        // 16384 = 128 tiles x 128 rows
#define NC (M_ROWS * C_DIM)              // 8,388,608

// ---------------------------------------------------------------------------
// Scratch (device globals; no runtime allocation allowed)
// ---------------------------------------------------------------------------
__device__ float  g_scratch[(size_t)M_ROWS * HID_DIM];
__device__ float  g_qs[(size_t)M_ROWS * C_DIM];
__device__ float  g_ks[(size_t)M_ROWS * C_DIM];
__device__ float  g_vs[(size_t)M_ROWS * C_DIM];
__device__ float  g_ob[(size_t)M_ROWS * C_DIM];
__device__ float  g_x1[(size_t)M_ROWS * C_DIM];
__device__ float  g_part[3 * NTILE * C_DIM > NTILE * HID_DIM ? 3 * NTILE * C_DIM : NTILE * HID_DIM];
__device__ float  g_mean[3 * C_DIM > HID_DIM ? 3 * C_DIM : HID_DIM];
__device__ float  g_rs[3 * C_DIM > HID_DIM ? 3 * C_DIM : HID_DIM];

// ---------------------------------------------------------------------------
// SGEMM: Y[M,N] = A[M,K] @ W[K,N] + bias. Double-buffered smem, 128x128x16,
// 8x8/thread, scalar ascending-k FFMA chain per output, bias added last.
// (FROZEN numerics; R13-proven structure, untouched.)
// grid.z selects (W,b) and output slice (merged q/k/v).
// ---------------------------------------------------------------------------
__global__ void __launch_bounds__(256)
sgemm_bias(const float* __restrict__ A,
           const float* __restrict__ W0, const float* __restrict__ W1,
           const float* __restrict__ W2,
           const float* __restrict__ b0, const float* __restrict__ b1,
           const float* __restrict__ b2,
           float* __restrict__ Y, int M, int N, int K, int ysl)
{
    const int BM = 128, BN = 128, BK = 16, TM = 8, TN = 8;
    __shared__ __align__(16) float As[2][BK][BM];
    __shared__ __align__(16) float Bs[2][BK][BN];

    const int tid = threadIdx.x;
    const int z   = blockIdx.z;
    const float* W    = (z == 0) ? W0 : (z == 1 ? W1 : W2);
    const float* bias = (z == 0) ? b0 : (z == 1 ? b1 : b2);
    float* Yz = Y + (size_t)z * ysl;

    const int trow = (tid / 16) * TM;
    const int tcol = (tid % 16) * TN;
    const float* Ab = A + (size_t)blockIdx.y * BM * K;
    const float* Wb = W + (size_t)blockIdx.x * BN;

    float4 ra[2], rb[2];

#define LOAD_TILE(kt)                                                        \
    {                                                                        \
        _Pragma("unroll")                                                    \
        for (int i = 0; i < 2; i++) {                                        \
            int idx4 = tid + 256 * i;                                        \
            int r  = idx4 >> 2, c4 = (idx4 & 3) * 4;                         \
            ra[i] = *reinterpret_cast<const float4*>(                        \
                &Ab[(size_t)r * K + (kt) * BK + c4]);                        \
            int r2 = idx4 >> 5, c42 = (idx4 & 31) * 4;                       \
            rb[i] = *reinterpret_cast<const float4*>(                        \
                &Wb[(size_t)((kt) * BK + r2) * N + c42]);                    \
        }                                                                    \
    }

#define STORE_TILE(buf)                                                      \
    {                                                                        \
        _Pragma("unroll")                                                    \
        for (int i = 0; i < 2; i++) {                                        \
            int idx4 = tid + 256 * i;                                        \
            int r  = idx4 >> 2, c4 = (idx4 & 3) * 4;                         \
            As[buf][c4 + 0][r] = ra[i].x;                                    \
            As[buf][c4 + 1][r] = ra[i].y;                                    \
            As[buf][c4 + 2][r] = ra[i].z;                                    \
            As[buf][c4 + 3][r] = ra[i].w;                                    \
            int r2 = idx4 >> 5, c42 = (idx4 & 31) * 4;                       \
            *reinterpret_cast<float4*>(&Bs[buf][r2][c42]) = rb[i];           \
        }                                                                    \
    }

    float acc[TM][TN];
#pragma unroll
    for (int i = 0; i < TM; i++)
#pragma unroll
        for (int j = 0; j < TN; j++) acc[i][j] = 0.f;

    LOAD_TILE(0);
    STORE_TILE(0);
    __syncthreads();

    const int nt = K / BK;
    for (int t = 0; t < nt; t++) {
        const int cur = t & 1;
        if (t + 1 < nt) LOAD_TILE(t + 1);

#pragma unroll
        for (int k = 0; k < BK; k++) {
            float4 a0 = *reinterpret_cast<const float4*>(&As[cur][k][trow]);
            float4 a1 = *reinterpret_cast<const float4*>(&As[cur][k][trow + 4]);
            float4 b0v = *reinterpret_cast<const float4*>(&Bs[cur][k][tcol]);
            float4 b1v = *reinterpret_cast<const float4*>(&Bs[cur][k][tcol + 4]);
            float a[8] = {a0.x, a0.y, a0.z, a0.w, a1.x, a1.y, a1.z, a1.w};
            float b[8] = {b0v.x, b0v.y, b0v.z, b0v.w, b1v.x, b1v.y, b1v.z, b1v.w};
#pragma unroll
            for (int i = 0; i < TM; i++)
#pragma unroll
                for (int j = 0; j < TN; j++)
                    acc[i][j] = __fmaf_rn(a[i], b[j], acc[i][j]);
        }

        if (t + 1 < nt) {
            STORE_TILE(cur ^ 1);
            __syncthreads();
        }
    }

#pragma unroll
    for (int i = 0; i < TM; i++) {
        size_t row = (size_t)blockIdx.y * BM + trow + i;
#pragma unroll
        for (int j = 0; j < TN; j++) {
            int col = blockIdx.x * BN + tcol + j;
            Yz[row * N + col] = __fadd_rn(acc[i][j], bias[col]);
        }
    }
#undef LOAD_TILE
#undef STORE_TILE
}

// ---------------------------------------------------------------------------
// BN stats (FROZEN numerics; vectorized thread mapping).
// Per-channel arithmetic identical to R13: rowlane partial = in-order fp32 sum
// of rows {ty, ty+32, ty+64, ty+96}; shfl-down tree (16..1) over rowlanes;
// stage2 same over 128 tile partials; mean=sum*2^-14; var on separately-
// rounded (x-mean)^2; rs=rsqrtf(var+1e-5f).
// New mapping only: each block covers 128 channels via float4 loads; each
// warp serially runs the 4 trees for its 4 channels.
// ---------------------------------------------------------------------------
__global__ void __launch_bounds__(1024)
bn_stage1(const float* __restrict__ Y, float* __restrict__ P, int C, int mode,
          int ysl)
{
    __shared__ float sm[32][132];
    const int z    = blockIdx.z;
    const int c0   = blockIdx.x * 128;
    const int tile = blockIdx.y;
    const int tx = threadIdx.x;   // channel-quad lane
    const int ty = threadIdx.y;   // row lane / warp id
    const float* Yz = Y + (size_t)z * ysl;
    float* Pz = P + (size_t)z * NTILE * C;

    float m[4];
    if (mode == 1) {
#pragma unroll
        for (int j = 0; j < 4; j++) m[j] = g_mean[z * C + c0 + 4 * tx + j];
    }

    float acc[4] = {0.f, 0.f, 0.f, 0.f};
#pragma unroll
    for (int i = 0; i < 4; i++) {
        int r = tile * 128 + ty + i * 32;
        float4 v4 = *reinterpret_cast<const float4*>(
            &Yz[(size_t)r * C + c0 + 4 * tx]);
        float v[4] = {v4.x, v4.y, v4.z, v4.w};
#pragma unroll
        for (int j = 0; j < 4; j++) {
            float val = v[j];
            if (mode == 1) {
                float d = __fsub_rn(val, m[j]);
                val = __fmul_rn(d, d);        // separate fp32 rounding
            }
            acc[j] = __fadd_rn(acc[j], val);
        }
    }
#pragma unroll
    for (int j = 0; j < 4; j++) sm[ty][4 * tx + j] = acc[j];
    __syncthreads();
    // warp ty reduces channels c0 + 4*ty + j; lane tx holds rowlane-tx partial
#pragma unroll
    for (int j = 0; j < 4; j++) {
        float v = sm[tx][4 * ty + j];
#pragma unroll
        for (int off = 16; off; off >>= 1)
            v = __fadd_rn(v, __shfl_down_sync(0xffffffffu, v, off));
        if (tx == 0)
            Pz[(size_t)tile * C + c0 + 4 * ty + j] = v;
    }
}

__global__ void __launch_bounds__(1024)
bn_stage2(const float* __restrict__ P, int C, int mode)
{
    __shared__ float sm[32][132];
    const int z  = blockIdx.z;
    const int c0 = blockIdx.x * 128;
    const int tx = threadIdx.x;
    const int ty = threadIdx.y;
    const float* Pz = P + (size_t)z * NTILE * C;

    float acc[4] = {0.f, 0.f, 0.f, 0.f};
#pragma unroll
    for (int i = 0; i < 4; i++) {
        int r = ty + i * 32;
        float4 v4 = *reinterpret_cast<const float4*>(
            &Pz[(size_t)r * C + c0 + 4 * tx]);
        acc[0] = __fadd_rn(acc[0], v4.x);
        acc[1] = __fadd_rn(acc[1], v4.y);
        acc[2] = __fadd_rn(acc[2], v4.z);
        acc[3] = __fadd_rn(acc[3], v4.w);
    }
#pragma unroll
    for (int j = 0; j < 4; j++) sm[ty][4 * tx + j] = acc[j];
    __syncthreads();
#pragma unroll
    for (int j = 0; j < 4; j++) {
        float v = sm[tx][4 * ty + j];
#pragma unroll
        for (int off = 16; off; off >>= 1)
            v = __fadd_rn(v, __shfl_down_sync(0xffffffffu, v, off));
        if (tx == 0) {
            float red = __fmul_rn(v, 6.103515625e-05f);   // /16384, exact
            if (mode == 0) {
                g_mean[z * C + c0 + 4 * ty + j] = red;
            } else {
                float arg = __fadd_rn(red, 1e-5f);
                g_rs[z * C + c0 + 4 * ty + j] = rsqrtf(arg);  // FROZEN
            }
        }
    }
}

// ---------------------------------------------------------------------------
// LIF over T=4 (FROZEN numerics) with optional fused residual add.
// grid.z variant for merged q/k/v (separate outputs + per-z gamma/beta/soff).
// ---------------------------------------------------------------------------
__global__ void lif_kernel(const float* __restrict__ Y, float* __restrict__ OUT,
                           const float* __restrict__ RES,
                           const float* __restrict__ gamma,
                           const float* __restrict__ beta,
                           int Cout, int use_bn, int soff)
{
    int idx = blockIdx.x * blockDim.x + threadIdx.x;
    int total = RN * Cout;
    if (idx >= total) return;
    int c = idx & (Cout - 1);
    float mean = 0.f, rs = 1.f, ga = 1.f, be = 0.f;
    if (use_bn) {
        mean = g_mean[soff + c]; rs = g_rs[soff + c];
        ga = gamma[c]; be = beta[c];
    }
    size_t stride = (size_t)RN * Cout;

    float mem = 0.f;
#pragma unroll
    for (int t = 0; t < T_DIM; t++) {
        size_t g = (size_t)t * stride + idx;
        float h = Y[g];
        float pre;
        if (use_bn) {
            float n1 = __fmul_rn(__fsub_rn(h, mean), rs);
            pre = __fmaf_rn(n1, ga, be);
        } else {
            pre = h;
        }
        mem = __fmaf_rn(__fsub_rn(pre, mem), 0.5f, mem);   // TAU=2
        float d = __fsub_rn(mem, 1.0f);
        float spk = (d > 0.f) ? 1.0f : 0.0f;
        if (spk > 0.f) mem = 0.f;
        OUT[g] = RES ? __fadd_rn(RES[g], spk) : spk;
    }
}

__global__ void lif_qkv(const float* __restrict__ Y,
                        float* __restrict__ O0, float* __restrict__ O1,
                        float* __restrict__ O2,
                        const float* __restrict__ g0, const float* __restrict__ g1,
                        const float* __restrict__ g2,
                        const float* __restrict__ be0, const float* __restrict__ be1,
                        const float* __restrict__ be2)
{
    int idx = blockIdx.x * blockDim.x + threadIdx.x;
    if (idx >= RN * C_DIM) return;
    const int z = blockIdx.y;
    const float* Yz = Y + (size_t)z * NC;
    float* OUT = (z == 0) ? O0 : (z == 1 ? O1 : O2);
    const float* gamma = (z == 0) ? g0 : (z == 1 ? g1 : g2);
    const float* beta  = (z == 0) ? be0 : (z == 1 ? be1 : be2);
    int c = idx & (C_DIM - 1);
    float mean = g_mean[z * C_DIM + c], rs = g_rs[z * C_DIM + c];
    float ga = gamma[c], be = beta[c];
    size_t stride = (size_t)RN * C_DIM;

    float mem = 0.f;
#pragma unroll
    for (int t = 0; t < T_DIM; t++) {
        size_t g = (size_t)t * stride + idx;
        float h = Yz[g];
        float n1 = __fmul_rn(__fsub_rn(h, mean), rs);
        float pre = __fmaf_rn(n1, ga, be);
        mem = __fmaf_rn(__fsub_rn(pre, mem), 0.5f, mem);
        float d = __fsub_rn(mem, 1.0f);
        float spk = (d > 0.f) ? 1.0f : 0.0f;
        if (spk > 0.f) mem = 0.f;
        OUT[g] = spk;
    }
}

// ---------------------------------------------------------------------------
// Spiking self-attention (exact integer arithmetic; FROZEN).
// ---------------------------------------------------------------------------
__global__ void __launch_bounds__(256)
attn_kernel(const float* __restrict__ Q, const float* __restrict__ K,
            const float* __restrict__ V, float* __restrict__ O)
{
    const int h  = blockIdx.x;
    const int tb = blockIdx.y;
    const size_t base = (size_t)tb * N_TOK * C_DIM + (size_t)h * HD;

    __shared__ float KV[64 * 64];
    __shared__ float pool[64 * 65];
    float* Ks = pool;
    float* Vs = pool + 2048;

    const int tid = threadIdx.x;

    float acc[16];
#pragma unroll
    for (int j = 0; j < 16; j++) acc[j] = 0.f;
    const int d1  = tid >> 2;
    const int d2b = (tid & 3) * 16;

    for (int n0 = 0; n0 < N_TOK; n0 += 32) {
#pragma unroll
        for (int i = tid; i < 32 * 64; i += 256) {
            int r = i >> 6, d = i & 63;
            size_t g = base + (size_t)(n0 + r) * C_DIM + d;
            Ks[i] = K[g];
            Vs[i] = V[g];
        }
        __syncthreads();
#pragma unroll
        for (int n = 0; n < 32; n++) {
            float a = Ks[n * 64 + d1];
#pragma unroll
            for (int j = 0; j < 16; j++)
                acc[j] += a * Vs[n * 64 + d2b + j];
        }
        __syncthreads();
    }
#pragma unroll
    for (int j = 0; j < 16; j++)
        KV[d1 * 64 + d2b + j] = acc[j];
    __syncthreads();

    const int trow = (tid >> 4) * 4;
    const int tcol = (tid & 15) * 4;
    float* Qs = pool;

    for (int rb = 0; rb < 4; rb++) {
#pragma unroll
        for (int i = tid; i < 64 * 64; i += 256) {
            int r = i >> 6, d = i & 63;
            Qs[r * 65 + d] = Q[base + (size_t)(rb * 64 + r) * C_DIM + d];
        }
        __syncthreads();

        float o[4][4];
#pragma unroll
        for (int i = 0; i < 4; i++)
#pragma unroll
            for (int j = 0; j < 4; j++) o[i][j] = 0.f;

#pragma unroll
        for (int k = 0; k < 64; k++) {
            float a[4], b[4];
#pragma unroll
            for (int i = 0; i < 4; i++) a[i] = Qs[(trow + i) * 65 + k];
#pragma unroll
            for (int j = 0; j < 4; j++) b[j] = KV[k * 64 + tcol + j];
#pragma unroll
            for (int i = 0; i < 4; i++)
#pragma unroll
                for (int j = 0; j < 4; j++)
                    o[i][j] += a[i] * b[j];
        }
#pragma unroll
        for (int i = 0; i < 4; i++)
#pragma unroll
            for (int j = 0; j < 4; j++)
                O[base + (size_t)(rb * 64 + trow + i) * C_DIM + tcol + j] = 0.125f * o[i][j];
        __syncthreads();
    }
}

// ---------------------------------------------------------------------------
// Launcher
// ---------------------------------------------------------------------------
static float* s_part = 0;

static void run_stats(const float* Y, int C, int zc, int ysl)
{
    dim3 sblk(32, 32);
    dim3 s1(C / 128, NTILE, zc);
    dim3 s2(C / 128, 1, zc);
    bn_stage1<<<s1, sblk>>>(Y, s_part, C, 0, ysl);
    bn_stage2<<<s2, sblk>>>(s_part, C, 0);
    bn_stage1<<<s1, sblk>>>(Y, s_part, C, 1, ysl);
    bn_stage2<<<s2, sblk>>>(s_part, C, 1);
}

extern "C" void kernel_launch(void* const* d_in, const int* in_sizes, int n_in,
                              void* d_out, int out_size)
{
    const float* x    = (const float*)d_in[0];
    const float* qW   = (const float*)d_in[1];
    const float* qb   = (const float*)d_in[2];
    const float* qg   = (const float*)d_in[3];
    const float* qbe  = (const float*)d_in[4];
    const float* kW   = (const float*)d_in[5];
    const float* kb   = (const float*)d_in[6];
    const float* kg   = (const float*)d_in[7];
    const float* kbe  = (const float*)d_in[8];
    const float* vW   = (const float*)d_in[9];
    const float* vb   = (const float*)d_in[10];
    const float* vg   = (const float*)d_in[11];
    const float* vbe  = (const float*)d_in[12];
    const float* pW   = (const float*)d_in[13];
    const float* pb   = (const float*)d_in[14];
    const float* pg   = (const float*)d_in[15];
    const float* pbe  = (const float*)d_in[16];
    const float* f1W  = (const float*)d_in[17];
    const float* f1b  = (const float*)d_in[18];
    const float* f1g  = (const float*)d_in[19];
    const float* f1be = (const float*)d_in[20];
    const float* f2W  = (const float*)d_in[21];
    const float* f2b  = (const float*)d_in[22];
    const float* f2g  = (const float*)d_in[23];
    const float* f2be = (const float*)d_in[24];
    float* out = (float*)d_out;

    float *scratch, *qs, *ks, *vs, *ob, *x1;
    cudaGetSymbolAddress((void**)&scratch, g_scratch);
    cudaGetSymbolAddress((void**)&qs, g_qs);
    cudaGetSymbolAddress((void**)&ks, g_ks);
    cudaGetSymbolAddress((void**)&vs, g_vs);
    cudaGetSymbolAddress((void**)&ob, g_ob);
    cudaGetSymbolAddress((void**)&x1, g_x1);
    cudaGetSymbolAddress((void**)&s_part, g_part);

    const int LIF_BLOCKS = (RN * C_DIM + 255) / 256;

    // --- SSA: q,k,v projections merged (grid.z=3) ---
    sgemm_bias<<<dim3(C_DIM / 128, M_ROWS / 128, 3), 256>>>(
        x, qW, kW, vW, qb, kb, vb, scratch, M_ROWS, C_DIM, C_DIM, NC);
    run_stats(scratch, C_DIM, 3, NC);
    lif_qkv<<<dim3(LIF_BLOCKS, 3), 256>>>(scratch, qs, ks, vs,
                                          qg, kg, vg, qbe, kbe, vbe);

    // --- attention + its LIF (exact) ---
    attn_kernel<<<dim3(H_HEADS, T_DIM * B_DIM), 256>>>(qs, ks, vs, ob);
    lif_kernel<<<LIF_BLOCKS, 256>>>(ob, ob, (const float*)0,
                                    (const float*)0, (const float*)0, C_DIM, 0, 0);

    // --- projection p; LIF fused with residual: x1 = x + spk ---
    sgemm_bias<<<dim3(C_DIM / 128, M_ROWS / 128, 1), 256>>>(
        ob, pW, pW, pW, pb, pb, pb, scratch, M_ROWS, C_DIM, C_DIM, 0);
    run_stats(scratch, C_DIM, 1, 0);
    lif_kernel<<<LIF_BLOCKS, 256>>>(scratch, x1, x, pg, pbe, C_DIM, 1, 0);

    // --- MLP f1 (512->2048), LIF in-place ---
    sgemm_bias<<<dim3(HID_DIM / 128, M_ROWS / 128, 1), 256>>>(
        x1, f1W, f1W, f1W, f1b, f1b, f1b, scratch, M_ROWS, HID_DIM, C_DIM, 0);
    run_stats(scratch, HID_DIM, 1, 0);
    lif_kernel<<<(RN * HID_DIM + 255) / 256, 256>>>(
        scratch, scratch, (const float*)0, f1g, f1be, HID_DIM, 1, 0);

    // --- MLP f2 (2048->512); LIF fused with final residual: out = x1 + spk ---
    sgemm_bias<<<dim3(C_DIM / 128, M_ROWS / 128, 1), 256>>>(
        scratch, f2W, f2W, f2W, f2b, f2b, f2b, vs, M_ROWS, C_DIM, HID_DIM, 0);
    run_stats(vs, C_DIM, 1, 0);
    lif_kernel<<<LIF_BLOCKS, 256>>>(vs, out, x1, f2g, f2be, C_DIM, 1, 0);
}

// round 17
// speedup vs baseline: 1.1038x; 1.0503x over previous
#include <cuda_runtime.h>
#include <math.h>

// Problem dims (fixed)
#define T_DIM 4
#define B_DIM 16
#define N_TOK 256
#define C_DIM 512
#define HID_DIM 2048
#define H_HEADS 8
#define HD 64
#define M_ROWS (T_DIM * B_DIM * N_TOK)   // 16384
#define RN (B_DIM * N_TOK)               // 4096
#define NTILE 128                        // 16384 = 128 tiles x 128 rows
#define NC (M_ROWS * C_DIM)              // 8,388,608

// ---------------------------------------------------------------------------
// Scratch (device globals; no runtime allocation allowed)
// ---------------------------------------------------------------------------
__device__ float  g_scratch[(size_t)M_ROWS * HID_DIM];
__device__ float  g_qs[(size_t)M_ROWS * C_DIM];
__device__ float  g_ks[(size_t)M_ROWS * C_DIM];
__device__ float  g_vs[(size_t)M_ROWS * C_DIM];
__device__ float  g_ob[(size_t)M_ROWS * C_DIM];
__device__ float  g_x1[(size_t)M_ROWS * C_DIM];
__device__ float  g_part[3 * NTILE * C_DIM > NTILE * HID_DIM ? 3 * NTILE * C_DIM : NTILE * HID_DIM];
__device__ float  g_mean[3 * C_DIM > HID_DIM ? 3 * C_DIM : HID_DIM];
__device__ float  g_rs[3 * C_DIM > HID_DIM ? 3 * C_DIM : HID_DIM];

// ---------------------------------------------------------------------------
// SGEMM: Y[M,N] = A[M,K] @ W[K,N] + bias. Double-buffered smem, 128x128x16,
// 8x8/thread, scalar ascending-k FFMA chain per output, bias added last.
// (FROZEN numerics; R13-proven structure, untouched.)
// grid.z selects (W,b) and output slice (merged q/k/v).
// ---------------------------------------------------------------------------
__global__ void __launch_bounds__(256)
sgemm_bias(const float* __restrict__ A,
           const float* __restrict__ W0, const float* __restrict__ W1,
           const float* __restrict__ W2,
           const float* __restrict__ b0, const float* __restrict__ b1,
           const float* __restrict__ b2,
           float* __restrict__ Y, int M, int N, int K, int ysl)
{
    const int BM = 128, BN = 128, BK = 16, TM = 8, TN = 8;
    __shared__ __align__(16) float As[2][BK][BM];
    __shared__ __align__(16) float Bs[2][BK][BN];

    const int tid = threadIdx.x;
    const int z   = blockIdx.z;
    const float* W    = (z == 0) ? W0 : (z == 1 ? W1 : W2);
    const float* bias = (z == 0) ? b0 : (z == 1 ? b1 : b2);
    float* Yz = Y + (size_t)z * ysl;

    const int trow = (tid / 16) * TM;
    const int tcol = (tid % 16) * TN;
    const float* Ab = A + (size_t)blockIdx.y * BM * K;
    const float* Wb = W + (size_t)blockIdx.x * BN;

    float4 ra[2], rb[2];

#define LOAD_TILE(kt)                                                        \
    {                                                                        \
        _Pragma("unroll")                                                    \
        for (int i = 0; i < 2; i++) {                                        \
            int idx4 = tid + 256 * i;                                        \
            int r  = idx4 >> 2, c4 = (idx4 & 3) * 4;                         \
            ra[i] = *reinterpret_cast<const float4*>(                        \
                &Ab[(size_t)r * K + (kt) * BK + c4]);                        \
            int r2 = idx4 >> 5, c42 = (idx4 & 31) * 4;                       \
            rb[i] = *reinterpret_cast<const float4*>(                        \
                &Wb[(size_t)((kt) * BK + r2) * N + c42]);                    \
        }                                                                    \
    }

#define STORE_TILE(buf)                                                      \
    {                                                                        \
        _Pragma("unroll")                                                    \
        for (int i = 0; i < 2; i++) {                                        \
            int idx4 = tid + 256 * i;                                        \
            int r  = idx4 >> 2, c4 = (idx4 & 3) * 4;                         \
            As[buf][c4 + 0][r] = ra[i].x;                                    \
            As[buf][c4 + 1][r] = ra[i].y;                                    \
            As[buf][c4 + 2][r] = ra[i].z;                                    \
            As[buf][c4 + 3][r] = ra[i].w;                                    \
            int r2 = idx4 >> 5, c42 = (idx4 & 31) * 4;                       \
            *reinterpret_cast<float4*>(&Bs[buf][r2][c42]) = rb[i];           \
        }                                                                    \
    }

    float acc[TM][TN];
#pragma unroll
    for (int i = 0; i < TM; i++)
#pragma unroll
        for (int j = 0; j < TN; j++) acc[i][j] = 0.f;

    LOAD_TILE(0);
    STORE_TILE(0);
    __syncthreads();

    const int nt = K / BK;
    for (int t = 0; t < nt; t++) {
        const int cur = t & 1;
        if (t + 1 < nt) LOAD_TILE(t + 1);

#pragma unroll
        for (int k = 0; k < BK; k++) {
            float4 a0 = *reinterpret_cast<const float4*>(&As[cur][k][trow]);
            float4 a1 = *reinterpret_cast<const float4*>(&As[cur][k][trow + 4]);
            float4 b0v = *reinterpret_cast<const float4*>(&Bs[cur][k][tcol]);
            float4 b1v = *reinterpret_cast<const float4*>(&Bs[cur][k][tcol + 4]);
            float a[8] = {a0.x, a0.y, a0.z, a0.w, a1.x, a1.y, a1.z, a1.w};
            float b[8] = {b0v.x, b0v.y, b0v.z, b0v.w, b1v.x, b1v.y, b1v.z, b1v.w};
#pragma unroll
            for (int i = 0; i < TM; i++)
#pragma unroll
                for (int j = 0; j < TN; j++)
                    acc[i][j] = __fmaf_rn(a[i], b[j], acc[i][j]);
        }

        if (t + 1 < nt) {
            STORE_TILE(cur ^ 1);
            __syncthreads();
        }
    }

#pragma unroll
    for (int i = 0; i < TM; i++) {
        size_t row = (size_t)blockIdx.y * BM + trow + i;
#pragma unroll
        for (int j = 0; j < TN; j++) {
            int col = blockIdx.x * BN + tcol + j;
            Yz[row * N + col] = __fadd_rn(acc[i][j], bias[col]);
        }
    }
#undef LOAD_TILE
#undef STORE_TILE
}

// ---------------------------------------------------------------------------
// BN stats (FROZEN numerics; vectorized mapping — verified bit-identical in
// R16). Per-channel arithmetic: rowlane partial = in-order fp32 sum of rows
// {ty,+32,+64,+96}; shfl-down tree (16..1); stage2 same over 128 partials;
// mean=sum*2^-14; var on separately-rounded (x-mean)^2; rs=rsqrtf(var+eps).
// ---------------------------------------------------------------------------
__global__ void __launch_bounds__(1024)
bn_stage1(const float* __restrict__ Y, float* __restrict__ P, int C, int mode,
          int ysl)
{
    __shared__ float sm[32][132];
    const int z    = blockIdx.z;
    const int c0   = blockIdx.x * 128;
    const int tile = blockIdx.y;
    const int tx = threadIdx.x;   // channel-quad lane
    const int ty = threadIdx.y;   // row lane / warp id
    const float* Yz = Y + (size_t)z * ysl;
    float* Pz = P + (size_t)z * NTILE * C;

    float m[4];
    if (mode == 1) {
#pragma unroll
        for (int j = 0; j < 4; j++) m[j] = g_mean[z * C + c0 + 4 * tx + j];
    }

    float acc[4] = {0.f, 0.f, 0.f, 0.f};
#pragma unroll
    for (int i = 0; i < 4; i++) {
        int r = tile * 128 + ty + i * 32;
        float4 v4 = *reinterpret_cast<const float4*>(
            &Yz[(size_t)r * C + c0 + 4 * tx]);
        float v[4] = {v4.x, v4.y, v4.z, v4.w};
#pragma unroll
        for (int j = 0; j < 4; j++) {
            float val = v[j];
            if (mode == 1) {
                float d = __fsub_rn(val, m[j]);
                val = __fmul_rn(d, d);        // separate fp32 rounding
            }
            acc[j] = __fadd_rn(acc[j], val);
        }
    }
#pragma unroll
    for (int j = 0; j < 4; j++) sm[ty][4 * tx + j] = acc[j];
    __syncthreads();
#pragma unroll
    for (int j = 0; j < 4; j++) {
        float v = sm[tx][4 * ty + j];
#pragma unroll
        for (int off = 16; off; off >>= 1)
            v = __fadd_rn(v, __shfl_down_sync(0xffffffffu, v, off));
        if (tx == 0)
            Pz[(size_t)tile * C + c0 + 4 * ty + j] = v;
    }
}

__global__ void __launch_bounds__(1024)
bn_stage2(const float* __restrict__ P, int C, int mode)
{
    __shared__ float sm[32][132];
    const int z  = blockIdx.z;
    const int c0 = blockIdx.x * 128;
    const int tx = threadIdx.x;
    const int ty = threadIdx.y;
    const float* Pz = P + (size_t)z * NTILE * C;

    float acc[4] = {0.f, 0.f, 0.f, 0.f};
#pragma unroll
    for (int i = 0; i < 4; i++) {
        int r = ty + i * 32;
        float4 v4 = *reinterpret_cast<const float4*>(
            &Pz[(size_t)r * C + c0 + 4 * tx]);
        acc[0] = __fadd_rn(acc[0], v4.x);
        acc[1] = __fadd_rn(acc[1], v4.y);
        acc[2] = __fadd_rn(acc[2], v4.z);
        acc[3] = __fadd_rn(acc[3], v4.w);
    }
#pragma unroll
    for (int j = 0; j < 4; j++) sm[ty][4 * tx + j] = acc[j];
    __syncthreads();
#pragma unroll
    for (int j = 0; j < 4; j++) {
        float v = sm[tx][4 * ty + j];
#pragma unroll
        for (int off = 16; off; off >>= 1)
            v = __fadd_rn(v, __shfl_down_sync(0xffffffffu, v, off));
        if (tx == 0) {
            float red = __fmul_rn(v, 6.103515625e-05f);   // /16384, exact
            if (mode == 0) {
                g_mean[z * C + c0 + 4 * ty + j] = red;
            } else {
                float arg = __fadd_rn(red, 1e-5f);
                g_rs[z * C + c0 + 4 * ty + j] = rsqrtf(arg);  // FROZEN
            }
        }
    }
}

// ---------------------------------------------------------------------------
// LIF over T=4 (FROZEN per-element numerics), vectorized: one thread = 4
// consecutive channels via float4 loads/stores. Optional fused residual add.
// ---------------------------------------------------------------------------
__global__ void lif_kernel(const float* __restrict__ Y, float* __restrict__ OUT,
                           const float* __restrict__ RES,
                           const float* __restrict__ gamma,
                           const float* __restrict__ beta,
                           int Cout, int use_bn, int soff)
{
    int q = blockIdx.x * blockDim.x + threadIdx.x;   // quad index
    int totalq = (RN * Cout) >> 2;
    if (q >= totalq) return;
    int base = q << 2;
    int c = base & (Cout - 1);
    float mean[4] = {0.f, 0.f, 0.f, 0.f}, rs[4] = {1.f, 1.f, 1.f, 1.f};
    float ga[4] = {1.f, 1.f, 1.f, 1.f}, be[4] = {0.f, 0.f, 0.f, 0.f};
    if (use_bn) {
#pragma unroll
        for (int j = 0; j < 4; j++) {
            mean[j] = g_mean[soff + c + j];
            rs[j]   = g_rs[soff + c + j];
            ga[j]   = gamma[c + j];
            be[j]   = beta[c + j];
        }
    }
    size_t stride = (size_t)RN * Cout;

    float mem[4] = {0.f, 0.f, 0.f, 0.f};
#pragma unroll
    for (int t = 0; t < T_DIM; t++) {
        size_t g = (size_t)t * stride + base;
        float4 h4 = *reinterpret_cast<const float4*>(&Y[g]);
        float h[4] = {h4.x, h4.y, h4.z, h4.w};
        float o[4];
#pragma unroll
        for (int j = 0; j < 4; j++) {
            float pre;
            if (use_bn) {
                float n1 = __fmul_rn(__fsub_rn(h[j], mean[j]), rs[j]);
                pre = __fmaf_rn(n1, ga[j], be[j]);
            } else {
                pre = h[j];
            }
            mem[j] = __fmaf_rn(__fsub_rn(pre, mem[j]), 0.5f, mem[j]); // TAU=2
            float d = __fsub_rn(mem[j], 1.0f);
            float spk = (d > 0.f) ? 1.0f : 0.0f;
            if (spk > 0.f) mem[j] = 0.f;
            o[j] = spk;
        }
        float4 o4;
        if (RES) {
            float4 r4 = *reinterpret_cast<const float4*>(&RES[g]);
            o4 = make_float4(__fadd_rn(r4.x, o[0]), __fadd_rn(r4.y, o[1]),
                             __fadd_rn(r4.z, o[2]), __fadd_rn(r4.w, o[3]));
        } else {
            o4 = make_float4(o[0], o[1], o[2], o[3]);
        }
        *reinterpret_cast<float4*>(&OUT[g]) = o4;
    }
}

// ---------------------------------------------------------------------------
// Spiking self-attention (exact integer arithmetic; FROZEN).
// ---------------------------------------------------------------------------
__global__ void __launch_bounds__(256)
attn_kernel(const float* __restrict__ Q, const float* __restrict__ K,
            const float* __restrict__ V, float* __restrict__ O)
{
    const int h  = blockIdx.x;
    const int tb = blockIdx.y;
    const size_t base = (size_t)tb * N_TOK * C_DIM + (size_t)h * HD;

    __shared__ float KV[64 * 64];
    __shared__ float pool[64 * 65];
    float* Ks = pool;
    float* Vs = pool + 2048;

    const int tid = threadIdx.x;

    float acc[16];
#pragma unroll
    for (int j = 0; j < 16; j++) acc[j] = 0.f;
    const int d1  = tid >> 2;
    const int d2b = (tid & 3) * 16;

    for (int n0 = 0; n0 < N_TOK; n0 += 32) {
#pragma unroll
        for (int i = tid; i < 32 * 64; i += 256) {
            int r = i >> 6, d = i & 63;
            size_t g = base + (size_t)(n0 + r) * C_DIM + d;
            Ks[i] = K[g];
            Vs[i] = V[g];
        }
        __syncthreads();
#pragma unroll
        for (int n = 0; n < 32; n++) {
            float a = Ks[n * 64 + d1];
#pragma unroll
            for (int j = 0; j < 16; j++)
                acc[j] += a * Vs[n * 64 + d2b + j];
        }
        __syncthreads();
    }
#pragma unroll
    for (int j = 0; j < 16; j++)
        KV[d1 * 64 + d2b + j] = acc[j];
    __syncthreads();

    const int trow = (tid >> 4) * 4;
    const int tcol = (tid & 15) * 4;
    float* Qs = pool;

    for (int rb = 0; rb < 4; rb++) {
#pragma unroll
        for (int i = tid; i < 64 * 64; i += 256) {
            int r = i >> 6, d = i & 63;
            Qs[r * 65 + d] = Q[base + (size_t)(rb * 64 + r) * C_DIM + d];
        }
        __syncthreads();

        float o[4][4];
#pragma unroll
        for (int i = 0; i < 4; i++)
#pragma unroll
            for (int j = 0; j < 4; j++) o[i][j] = 0.f;

#pragma unroll
        for (int k = 0; k < 64; k++) {
            float a[4], b[4];
#pragma unroll
            for (int i = 0; i < 4; i++) a[i] = Qs[(trow + i) * 65 + k];
#pragma unroll
            for (int j = 0; j < 4; j++) b[j] = KV[k * 64 + tcol + j];
#pragma unroll
            for (int i = 0; i < 4; i++)
#pragma unroll
                for (int j = 0; j < 4; j++)
                    o[i][j] += a[i] * b[j];
        }
#pragma unroll
        for (int i = 0; i < 4; i++)
#pragma unroll
            for (int j = 0; j < 4; j++)
                O[base + (size_t)(rb * 64 + trow + i) * C_DIM + tcol + j] = 0.125f * o[i][j];
        __syncthreads();
    }
}

// ---------------------------------------------------------------------------
// Launcher
// ---------------------------------------------------------------------------
static float* s_part = 0;

static void run_stats(const float* Y, int C, int zc, int ysl)
{
    dim3 sblk(32, 32);
    dim3 s1(C / 128, NTILE, zc);
    dim3 s2(C / 128, 1, zc);
    bn_stage1<<<s1, sblk>>>(Y, s_part, C, 0, ysl);
    bn_stage2<<<s2, sblk>>>(s_part, C, 0);
    bn_stage1<<<s1, sblk>>>(Y, s_part, C, 1, ysl);
    bn_stage2<<<s2, sblk>>>(s_part, C, 1);
}

extern "C" void kernel_launch(void* const* d_in, const int* in_sizes, int n_in,
                              void* d_out, int out_size)
{
    const float* x    = (const float*)d_in[0];
    const float* qW   = (const float*)d_in[1];
    const float* qb   = (const float*)d_in[2];
    const float* qg   = (const float*)d_in[3];
    const float* qbe  = (const float*)d_in[4];
    const float* kW   = (const float*)d_in[5];
    const float* kb   = (const float*)d_in[6];
    const float* kg   = (const float*)d_in[7];
    const float* kbe  = (const float*)d_in[8];
    const float* vW   = (const float*)d_in[9];
    const float* vb   = (const float*)d_in[10];
    const float* vg   = (const float*)d_in[11];
    const float* vbe  = (const float*)d_in[12];
    const float* pW   = (const float*)d_in[13];
    const float* pb   = (const float*)d_in[14];
    const float* pg   = (const float*)d_in[15];
    const float* pbe  = (const float*)d_in[16];
    const float* f1W  = (const float*)d_in[17];
    const float* f1b  = (const float*)d_in[18];
    const float* f1g  = (const float*)d_in[19];
    const float* f1be = (const float*)d_in[20];
    const float* f2W  = (const float*)d_in[21];
    const float* f2b  = (const float*)d_in[22];
    const float* f2g  = (const float*)d_in[23];
    const float* f2be = (const float*)d_in[24];
    float* out = (float*)d_out;

    float *scratch, *qs, *ks, *vs, *ob, *x1;
    cudaGetSymbolAddress((void**)&scratch, g_scratch);
    cudaGetSymbolAddress((void**)&qs, g_qs);
    cudaGetSymbolAddress((void**)&ks, g_ks);
    cudaGetSymbolAddress((void**)&vs, g_vs);
    cudaGetSymbolAddress((void**)&ob, g_ob);
    cudaGetSymbolAddress((void**)&x1, g_x1);
    cudaGetSymbolAddress((void**)&s_part, g_part);

    const int LIFQ_BLOCKS  = (RN * C_DIM / 4 + 255) / 256;    // vectorized
    const int LIFQ_BLOCKS2 = (RN * HID_DIM / 4 + 255) / 256;

    // --- SSA: q,k,v projections merged (grid.z=3) ---
    sgemm_bias<<<dim3(C_DIM / 128, M_ROWS / 128, 3), 256>>>(
        x, qW, kW, vW, qb, kb, vb, scratch, M_ROWS, C_DIM, C_DIM, NC);
    run_stats(scratch, C_DIM, 3, NC);
    lif_kernel<<<LIFQ_BLOCKS, 256>>>(scratch,                  qs, (const float*)0, qg, qbe, C_DIM, 1, 0);
    lif_kernel<<<LIFQ_BLOCKS, 256>>>(scratch + (size_t)NC,     ks, (const float*)0, kg, kbe, C_DIM, 1, C_DIM);
    lif_kernel<<<LIFQ_BLOCKS, 256>>>(scratch + (size_t)2 * NC, vs, (const float*)0, vg, vbe, C_DIM, 1, 2 * C_DIM);

    // --- attention + its LIF (exact) ---
    attn_kernel<<<dim3(H_HEADS, T_DIM * B_DIM), 256>>>(qs, ks, vs, ob);
    lif_kernel<<<LIFQ_BLOCKS, 256>>>(ob, ob, (const float*)0,
                                     (const float*)0, (const float*)0, C_DIM, 0, 0);

    // --- projection p; LIF fused with residual: x1 = x + spk ---
    sgemm_bias<<<dim3(C_DIM / 128, M_ROWS / 128, 1), 256>>>(
        ob, pW, pW, pW, pb, pb, pb, scratch, M_ROWS, C_DIM, C_DIM, 0);
    run_stats(scratch, C_DIM, 1, 0);
    lif_kernel<<<LIFQ_BLOCKS, 256>>>(scratch, x1, x, pg, pbe, C_DIM, 1, 0);

    // --- MLP f1 (512->2048), LIF in-place ---
    sgemm_bias<<<dim3(HID_DIM / 128, M_ROWS / 128, 1), 256>>>(
        x1, f1W, f1W, f1W, f1b, f1b, f1b, scratch, M_ROWS, HID_DIM, C_DIM, 0);
    run_stats(scratch, HID_DIM, 1, 0);
    lif_kernel<<<LIFQ_BLOCKS2, 256>>>(
        scratch, scratch, (const float*)0, f1g, f1be, HID_DIM, 1, 0);

    // --- MLP f2 (2048->512); LIF fused with final residual: out = x1 + spk ---
    sgemm_bias<<<dim3(C_DIM / 128, M_ROWS / 128, 1), 256>>>(
        scratch, f2W, f2W, f2W, f2b, f2b, f2b, vs, M_ROWS, C_DIM, HID_DIM, 0);
    run_stats(vs, C_DIM, 1, 0);
    lif_kernel<<<LIFQ_BLOCKS, 256>>>(vs, out, x1, f2g, f2be, C_DIM, 1, 0);
}